// round 9
// baseline (speedup 1.0000x reference)
#include <cuda_runtime.h>
#include <cstdint>

// FocalLoss: loss = sum_b mean_a [ w[a] * (1-p)^2 * BCE(clamp(p), t) ]
// inputs [B, A] f32, targets [A, B] i32 (0/1), w [A] f32 -> scalar f32
//
// vs R7 (55.4us): identical except the smem input tile is stored TRANSPOSED
// with odd row stride 257 (float4 units): phys(b,a4) = a4*257 + b.
//   reads  (a4*257 + tid): lane-consecutive -> conflict-free LDS.128
//   writes (cp.async dst): same-b 10-lane groups -> 2-way max (odd stride)
// This removes the 8-way read conflict that made the smem crossbar
// (~42us/SM) co-limiting with the ~50us DRAM stream.
constexpr int BVAL = 1000000;
constexpr int AVAL = 40;
constexpr float EPSF = 1e-12f;
constexpr int TPB = 256;
constexpr int GRID = (BVAL + TPB - 1) / TPB;        // 3907
constexpr int ROW_F4 = AVAL / 4;                    // 10 float4 per b-row
constexpr int TILE_F4 = TPB * ROW_F4;               // 2560 chunks per block
constexpr int TSTRIDE = 257;                        // odd f4 stride (transposed rows)
constexpr int SMEM_F4 = (ROW_F4 - 1) * TSTRIDE + TPB;   // 2569 f4 = 41.1 KB
constexpr long TOTAL_F4 = (long)BVAL * ROW_F4;      // 10e6

__device__ double g_acc;   // zero at module load; reset by finalize each launch

__device__ __forceinline__ uint32_t smem_u32(const void* p) {
    uint32_t a;
    asm("{ .reg .u64 t; cvta.to.shared.u64 t, %1; cvt.u32.u64 %0, t; }"
        : "=r"(a) : "l"(p));
    return a;
}

__global__ void __launch_bounds__(TPB) focal_main_kernel(
    const float* __restrict__ inputs,
    const int*   __restrict__ targets,
    const float* __restrict__ w)
{
    __shared__ float4 s4[SMEM_F4];     // transposed tile: phys = a4*257 + b_local
    __shared__ float  sw[AVAL];

    int tid = threadIdx.x;
    if (tid < AVAL) sw[tid] = w[tid];

    // Stage input slab. GMEM side: lane-contiguous 16B chunks (s = tid + i*256).
    // SMEM side: transposed dst a4*257 + b_local, 2-way conflict max.
    long base_f4 = (long)blockIdx.x * TILE_F4;
    const float4* in4 = reinterpret_cast<const float4*>(inputs);
    #pragma unroll
    for (int i = 0; i < ROW_F4; i++) {
        int  s    = tid + i * TPB;          // chunk id within tile
        int  bl   = s / ROW_F4;             // local b row
        int  a4   = s - bl * ROW_F4;        // column block
        int  dstf = a4 * TSTRIDE + bl;      // transposed f4 index
        long gidx = base_f4 + s;
        if (gidx < TOTAL_F4) {
            uint32_t dst = smem_u32(&s4[dstf]);
            asm volatile("cp.async.cg.shared.global [%0], [%1], 16;"
                         :: "r"(dst), "l"(in4 + gidx) : "memory");
        } else {
            s4[dstf] = make_float4(0.f, 0.f, 0.f, 0.f);
        }
    }
    asm volatile("cp.async.commit_group;" ::: "memory");
    asm volatile("cp.async.wait_group 0;" ::: "memory");
    __syncthreads();

    int b = blockIdx.x * TPB + tid;
    float acc = 0.0f;
    if (b < BVAL) {
        #pragma unroll
        for (int a4 = 0; a4 < ROW_F4; a4++) {
            float4 p4 = s4[a4 * TSTRIDE + tid];          // conflict-free LDS.128
            float pv[4] = {p4.x, p4.y, p4.z, p4.w};
            #pragma unroll
            for (int j = 0; j < 4; j++) {
                int a = a4 * 4 + j;
                int t = __ldg(targets + (long)a * BVAL + b);  // coalesced per a
                float p  = pv[j];
                float pc = fminf(fmaxf(p, EPSF), 1.0f - EPSF);
                float arg = t ? pc : (1.0f - pc);   // t is 0/1: one log suffices
                float bce = -__logf(arg);           // MUFU.LG2 path
                float om  = 1.0f - p;               // focal weight uses UNCLAMPED p
                acc = fmaf(sw[a] * om * om, bce, acc);
            }
        }
    }

    // warp reduce
    #pragma unroll
    for (int off = 16; off; off >>= 1)
        acc += __shfl_down_sync(0xffffffffu, acc, off);

    __shared__ float warpsum[TPB / 32];
    if ((tid & 31) == 0) warpsum[tid >> 5] = acc;
    __syncthreads();

    if (tid < TPB / 32) {
        float v = warpsum[tid];
        #pragma unroll
        for (int off = (TPB / 64); off; off >>= 1)
            v += __shfl_down_sync(0xffu, v, off);
        if (tid == 0) atomicAdd(&g_acc, (double)v);
    }
}

__global__ void finalize_kernel(float* __restrict__ out) {
    out[0] = (float)(g_acc * (1.0 / (double)AVAL));
    g_acc = 0.0;   // self-reset: next graph replay starts from zero
}

extern "C" void kernel_launch(void* const* d_in, const int* in_sizes, int n_in,
                              void* d_out, int out_size)
{
    const float* inputs  = (const float*)d_in[0];   // [B, A]
    const int*   targets = (const int*)  d_in[1];   // [A, B]
    const float* weights = (const float*)d_in[2];   // [A]

    focal_main_kernel<<<GRID, TPB>>>(inputs, targets, weights);
    finalize_kernel<<<1, 1>>>((float*)d_out);
}

// round 10
// speedup vs baseline: 1.1542x; 1.1542x over previous
#include <cuda_runtime.h>
#include <cstdint>

// FocalLoss: loss = sum_b mean_a [ w[a] * (1-p)^2 * BCE(clamp(p), t) ]
// inputs [B, A] f32, targets [A, B] i32 (0/1), w [A] f32 -> scalar f32
//
// Base = R7 (measured best, 55.4us): smem-staged input slab via lane-
// contiguous cp.async.cg (L2-only), targets direct coalesced loads, one
// MUFU log per element, atomicAdd(double) tail + self-resetting finalize.
// Single change vs R7: targets use __ldcs (evict-first streaming) so the
// once-read 160MB target stream does not thrash L2 against the input stream.
constexpr int BVAL = 1000000;
constexpr int AVAL = 40;
constexpr float EPSF = 1e-12f;
constexpr int TPB = 256;
constexpr int GRID = (BVAL + TPB - 1) / TPB;        // 3907
constexpr int ROW_F4 = AVAL / 4;                    // 10 float4 per row
constexpr int TILE_F4 = TPB * ROW_F4;               // 2560 float4 per block
constexpr long TOTAL_F4 = (long)BVAL * ROW_F4;      // 10e6

__device__ double g_acc;   // zero at module load; reset by finalize each launch

__device__ __forceinline__ uint32_t smem_u32(const void* p) {
    uint32_t a;
    asm("{ .reg .u64 t; cvta.to.shared.u64 t, %1; cvt.u32.u64 %0, t; }"
        : "=r"(a) : "l"(p));
    return a;
}

__global__ void __launch_bounds__(TPB) focal_main_kernel(
    const float* __restrict__ inputs,
    const int*   __restrict__ targets,
    const float* __restrict__ w)
{
    __shared__ float4 s4[TILE_F4];     // 40 KB: block's 256 input rows
    __shared__ float  sw[AVAL];

    int tid = threadIdx.x;
    if (tid < AVAL) sw[tid] = w[tid];

    // Stage the block's input slab: lane-contiguous 16B async copies.
    long base_f4 = (long)blockIdx.x * TILE_F4;
    const float4* in4 = reinterpret_cast<const float4*>(inputs);
    #pragma unroll
    for (int i = 0; i < ROW_F4; i++) {
        int  sidx = tid + i * TPB;
        long gidx = base_f4 + sidx;
        if (gidx < TOTAL_F4) {
            uint32_t dst = smem_u32(&s4[sidx]);
            asm volatile("cp.async.cg.shared.global [%0], [%1], 16;"
                         :: "r"(dst), "l"(in4 + gidx) : "memory");
        } else {
            s4[sidx] = make_float4(0.f, 0.f, 0.f, 0.f);
        }
    }
    asm volatile("cp.async.commit_group;" ::: "memory");
    asm volatile("cp.async.wait_group 0;" ::: "memory");
    __syncthreads();

    int b = blockIdx.x * TPB + tid;
    float acc = 0.0f;
    if (b < BVAL) {
        #pragma unroll
        for (int a4 = 0; a4 < ROW_F4; a4++) {
            float4 p4 = s4[tid * ROW_F4 + a4];          // own row from smem
            float pv[4] = {p4.x, p4.y, p4.z, p4.w};
            #pragma unroll
            for (int j = 0; j < 4; j++) {
                int a = a4 * 4 + j;
                int t = __ldcs(targets + (long)a * BVAL + b);  // streaming, evict-first
                float p  = pv[j];
                float pc = fminf(fmaxf(p, EPSF), 1.0f - EPSF);
                float arg = t ? pc : (1.0f - pc);   // t is 0/1: one log suffices
                float bce = -__logf(arg);           // MUFU.LG2 path
                float om  = 1.0f - p;               // focal weight uses UNCLAMPED p
                acc = fmaf(sw[a] * om * om, bce, acc);
            }
        }
    }

    // warp reduce
    #pragma unroll
    for (int off = 16; off; off >>= 1)
        acc += __shfl_down_sync(0xffffffffu, acc, off);

    __shared__ float warpsum[TPB / 32];
    if ((tid & 31) == 0) warpsum[tid >> 5] = acc;
    __syncthreads();

    if (tid < TPB / 32) {
        float v = warpsum[tid];
        #pragma unroll
        for (int off = (TPB / 64); off; off >>= 1)
            v += __shfl_down_sync(0xffu, v, off);
        if (tid == 0) atomicAdd(&g_acc, (double)v);
    }
}

__global__ void finalize_kernel(float* __restrict__ out) {
    out[0] = (float)(g_acc * (1.0 / (double)AVAL));
    g_acc = 0.0;   // self-reset: next graph replay starts from zero
}

extern "C" void kernel_launch(void* const* d_in, const int* in_sizes, int n_in,
                              void* d_out, int out_size)
{
    const float* inputs  = (const float*)d_in[0];   // [B, A]
    const int*   targets = (const int*)  d_in[1];   // [A, B]
    const float* weights = (const float*)d_in[2];   // [A]

    focal_main_kernel<<<GRID, TPB>>>(inputs, targets, weights);
    finalize_kernel<<<1, 1>>>((float*)d_out);
}

// round 11
// speedup vs baseline: 1.1900x; 1.0310x over previous
#include <cuda_runtime.h>
#include <cstdint>

// FocalLoss: loss = sum_b mean_a [ w[a] * (1-p)^2 * BCE(clamp(p), t) ]
// inputs [B, A] f32, targets [A, B] i32 (0/1), w [A] f32 -> scalar f32
//
// Single fused kernel (1 graph node). Mainloop = measured-best R7/R9:
// smem-staged input slab via lane-contiguous cp.async.cg, coalesced target
// loads, one MUFU log per element, atomicAdd(double) global accumulate.
// Tail: release-scope atom.inc on a wrapping block counter (NO threadfence,
// no L1 flush -- that was R2's mistake); last block's tid0 acquire-loads
// g_acc, writes out, resets g_acc. Counter self-resets by wrap -> every
// graph replay is deterministic.
constexpr int BVAL = 1000000;
constexpr int AVAL = 40;
constexpr float EPSF = 1e-12f;
constexpr int TPB = 256;
constexpr int GRID = (BVAL + TPB - 1) / TPB;        // 3907
constexpr int ROW_F4 = AVAL / 4;                    // 10 float4 per row
constexpr int TILE_F4 = TPB * ROW_F4;               // 2560 float4 per block
constexpr long TOTAL_F4 = (long)BVAL * ROW_F4;      // 10e6

__device__ double g_acc;            // zero at load; reset by last block each launch
__device__ unsigned int g_count;    // zero at load; self-resets via inc-wrap

__device__ __forceinline__ uint32_t smem_u32(const void* p) {
    uint32_t a;
    asm("{ .reg .u64 t; cvta.to.shared.u64 t, %1; cvt.u32.u64 %0, t; }"
        : "=r"(a) : "l"(p));
    return a;
}

__global__ void __launch_bounds__(TPB) focal_fused_kernel(
    const float* __restrict__ inputs,
    const int*   __restrict__ targets,
    const float* __restrict__ w,
    float* __restrict__ out)
{
    __shared__ float4 s4[TILE_F4];     // 40 KB: block's 256 input rows
    __shared__ float  sw[AVAL];

    int tid = threadIdx.x;
    if (tid < AVAL) sw[tid] = w[tid];

    // Stage the block's input slab: lane-contiguous 16B async copies.
    long base_f4 = (long)blockIdx.x * TILE_F4;
    const float4* in4 = reinterpret_cast<const float4*>(inputs);
    #pragma unroll
    for (int i = 0; i < ROW_F4; i++) {
        int  sidx = tid + i * TPB;
        long gidx = base_f4 + sidx;
        if (gidx < TOTAL_F4) {
            uint32_t dst = smem_u32(&s4[sidx]);
            asm volatile("cp.async.cg.shared.global [%0], [%1], 16;"
                         :: "r"(dst), "l"(in4 + gidx) : "memory");
        } else {
            s4[sidx] = make_float4(0.f, 0.f, 0.f, 0.f);
        }
    }
    asm volatile("cp.async.commit_group;" ::: "memory");
    asm volatile("cp.async.wait_group 0;" ::: "memory");
    __syncthreads();

    int b = blockIdx.x * TPB + tid;
    float acc = 0.0f;
    if (b < BVAL) {
        #pragma unroll
        for (int a4 = 0; a4 < ROW_F4; a4++) {
            float4 p4 = s4[tid * ROW_F4 + a4];          // own row from smem
            float pv[4] = {p4.x, p4.y, p4.z, p4.w};
            #pragma unroll
            for (int j = 0; j < 4; j++) {
                int a = a4 * 4 + j;
                int t = __ldcs(targets + (long)a * BVAL + b);  // coalesced per a
                float p  = pv[j];
                float pc = fminf(fmaxf(p, EPSF), 1.0f - EPSF);
                float arg = t ? pc : (1.0f - pc);   // t is 0/1: one log suffices
                float bce = -__logf(arg);           // MUFU.LG2 path
                float om  = 1.0f - p;               // focal weight uses UNCLAMPED p
                acc = fmaf(sw[a] * om * om, bce, acc);
            }
        }
    }

    // warp reduce
    #pragma unroll
    for (int off = 16; off; off >>= 1)
        acc += __shfl_down_sync(0xffffffffu, acc, off);

    __shared__ float warpsum[TPB / 32];
    if ((tid & 31) == 0) warpsum[tid >> 5] = acc;
    __syncthreads();

    if (tid < TPB / 32) {
        float v = warpsum[tid];
        #pragma unroll
        for (int off = (TPB / 64); off; off >>= 1)
            v += __shfl_down_sync(0xffu, v, off);
        if (tid == 0) {
            atomicAdd(&g_acc, (double)v);
            // Release-scope wrapping inc: orders the g_acc add, no L1 flush.
            // Wraps to 0 at GRID-1 -> deterministic across graph replays.
            unsigned int old;
            asm volatile("atom.release.gpu.global.inc.u32 %0, [%1], %2;"
                         : "=r"(old)
                         : "l"(&g_count), "r"((unsigned)(GRID - 1))
                         : "memory");
            if (old == (unsigned)(GRID - 1)) {
                // Last block: all 3907 release-incs done -> all adds visible.
                double tot;
                asm volatile("ld.acquire.gpu.global.f64 %0, [%1];"
                             : "=d"(tot) : "l"(&g_acc) : "memory");
                out[0] = (float)(tot * (1.0 / (double)AVAL));
                asm volatile("st.relaxed.gpu.global.f64 [%0], %1;"
                             :: "l"(&g_acc), "d"(0.0) : "memory");
            }
        }
    }
}

extern "C" void kernel_launch(void* const* d_in, const int* in_sizes, int n_in,
                              void* d_out, int out_size)
{
    const float* inputs  = (const float*)d_in[0];   // [B, A]
    const int*   targets = (const int*)  d_in[1];   // [A, B]
    const float* weights = (const float*)d_in[2];   // [A]

    focal_fused_kernel<<<GRID, TPB>>>(inputs, targets, weights, (float*)d_out);
}